// round 2
// baseline (speedup 1.0000x reference)
#include <cuda_runtime.h>
#include <cuda_bf16.h>
#include <math.h>

#define N_TOKENS 131072
#define EMB_DIM  64
#define N_CODES  1024
#define DECAY_F       0.99f
#define OMD_F         ((float)(1.0 - 0.99))     /* matches python 1.0-DECAY cast to f32 */
#define EPS_F         1e-5f
#define COMMIT_HALF   0.125f                     /* 0.25 * 0.5 */

// ---------------- device scratch (no allocations allowed) ----------------
__device__ int   g_idx[N_TOKENS];
__device__ float g_counts[N_CODES];
__device__ float g_dw[N_CODES * EMB_DIM];
__device__ float g_h[N_CODES];            // 0.5 * ||e_k||^2
__device__ float g_cs[N_CODES];           // smoothed cluster size
__device__ float g_embed_new[N_CODES * EMB_DIM];
__device__ float g_loss_accum;

// ---------------- packed f32x2 helpers ----------------
__device__ __forceinline__ unsigned long long fma2(unsigned long long a,
                                                   unsigned long long b,
                                                   unsigned long long c) {
    unsigned long long d;
    asm("fma.rn.f32x2 %0, %1, %2, %3;" : "=l"(d) : "l"(a), "l"(b), "l"(c));
    return d;
}
__device__ __forceinline__ unsigned long long pack2(float lo, float hi) {
    unsigned long long r;
    asm("mov.b64 %0, {%1, %2};" : "=l"(r) : "f"(lo), "f"(hi));
    return r;
}
__device__ __forceinline__ float2 unpack2(unsigned long long v) {
    float lo, hi;
    asm("mov.b64 {%0, %1}, %2;" : "=f"(lo), "=f"(hi) : "l"(v));
    return make_float2(lo, hi);
}

// ---------------- kernel 1: zero scratch ----------------
__global__ void zero_scratch_kernel() {
    int i = blockIdx.x * blockDim.x + threadIdx.x;
    if (i < N_CODES) g_counts[i] = 0.0f;
    if (i < N_CODES * EMB_DIM) g_dw[i] = 0.0f;
    if (i == 0) g_loss_accum = 0.0f;
}

// ---------------- kernel 2: h_k = 0.5*||e_k||^2 ----------------
__global__ void prep_h_kernel(const float* __restrict__ e) {
    int k = blockIdx.x * blockDim.x + threadIdx.x;
    if (k >= N_CODES) return;
    const float4* row = (const float4*)(e + (size_t)k * EMB_DIM);
    float s = 0.0f;
#pragma unroll
    for (int j = 0; j < 16; j++) {
        float4 v = row[j];
        s = fmaf(v.x, v.x, s); s = fmaf(v.y, v.y, s);
        s = fmaf(v.z, v.z, s); s = fmaf(v.w, v.w, s);
    }
    g_h[k] = 0.5f * s;
}

// fp64 re-resolution: val = x.e - 0.5||e||^2 in double
__device__ double ddot_val(const unsigned long long* x2, const float* __restrict__ e) {
    double dot = 0.0, h = 0.0;
#pragma unroll
    for (int j = 0; j < 32; j++) {
        float2 xv = unpack2(x2[j]);
        double e0 = (double)e[2 * j];
        double e1 = (double)e[2 * j + 1];
        dot += (double)xv.x * e0 + (double)xv.y * e1;
        h   += e0 * e0 + e1 * e1;
    }
    return dot - 0.5 * h;
}

// ---------------- kernel 3: per-token argmin + scatter ----------------
#define TPB  128
#define TILE 64
__global__ __launch_bounds__(TPB)
void argmin_kernel(const float* __restrict__ x_g,
                   const float* __restrict__ e_g,
                   float* __restrict__ enc_out) {
    __shared__ float sh_e[TILE * EMB_DIM];
    __shared__ float sh_h[TILE];

    int t = blockIdx.x * TPB + threadIdx.x;

    // load token into packed f32x2 registers
    unsigned long long x2[32];
    {
        const float4* xr = (const float4*)(x_g + (size_t)t * EMB_DIM);
#pragma unroll
        for (int j = 0; j < 16; j++) {
            float4 v = xr[j];
            x2[2 * j]     = pack2(v.x, v.y);
            x2[2 * j + 1] = pack2(v.z, v.w);
        }
    }

    float best1 = -3.4e38f, best2 = -3.4e38f;
    int idx1 = 0, idx2 = 0;

    for (int tile = 0; tile < N_CODES / TILE; ++tile) {
        __syncthreads();
        // stage 64 codes into shared
        {
            const float4* src = (const float4*)(e_g + (size_t)tile * TILE * EMB_DIM);
            float4* dst = (float4*)sh_e;
#pragma unroll 2
            for (int j = threadIdx.x; j < TILE * 16; j += TPB) dst[j] = src[j];
            if (threadIdx.x < TILE) sh_h[threadIdx.x] = g_h[tile * TILE + threadIdx.x];
        }
        __syncthreads();

#pragma unroll 2
        for (int kk = 0; kk < TILE; ++kk) {
            const ulonglong2* er = (const ulonglong2*)(sh_e + kk * EMB_DIM);
            unsigned long long a0 = 0ull, a1 = 0ull, a2 = 0ull, a3 = 0ull;
#pragma unroll
            for (int j = 0; j < 16; j += 2) {
                ulonglong2 v0 = er[j];
                ulonglong2 v1 = er[j + 1];
                a0 = fma2(x2[2 * j],     v0.x, a0);
                a1 = fma2(x2[2 * j + 1], v0.y, a1);
                a2 = fma2(x2[2 * j + 2], v1.x, a2);
                a3 = fma2(x2[2 * j + 3], v1.y, a3);
            }
            float2 f0 = unpack2(a0), f1 = unpack2(a1);
            float2 f2 = unpack2(a2), f3 = unpack2(a3);
            float dot = ((f0.x + f0.y) + (f1.x + f1.y)) +
                        ((f2.x + f2.y) + (f3.x + f3.y));
            float val = dot - sh_h[kk];
            int k = tile * TILE + kk;
            if (val > best1) { best2 = best1; idx2 = idx1; best1 = val; idx1 = k; }
            else if (val > best2) { best2 = val; idx2 = k; }
        }
    }

    // near-tie: re-resolve the top-2 in fp64 (rare path)
    if (best1 - best2 < 1e-2f) {
        double v1 = ddot_val(x2, e_g + (size_t)idx1 * EMB_DIM);
        double v2 = ddot_val(x2, e_g + (size_t)idx2 * EMB_DIM);
        if (v2 > v1 || (v2 == v1 && idx2 < idx1)) idx1 = idx2;
    }

    g_idx[t] = idx1;
    atomicAdd(&g_counts[idx1], 1.0f);
    float* dwrow = &g_dw[(size_t)idx1 * EMB_DIM];
#pragma unroll
    for (int j = 0; j < 32; j++) {
        float2 p = unpack2(x2[j]);
        atomicAdd(&dwrow[2 * j],     p.x);
        atomicAdd(&dwrow[2 * j + 1], p.y);
    }
    enc_out[(size_t)t * N_CODES + idx1] = 1.0f;
}

// ---------------- kernel 4: EMA cluster stats + perplexity ----------------
__global__ void stats_kernel(const float* __restrict__ ema_cs,
                             float* __restrict__ out_perp) {
    __shared__ float sh[N_CODES];
    int k = threadIdx.x;
    float cnt = g_counts[k];
    float cs = ema_cs[k] * DECAY_F + OMD_F * cnt;
    sh[k] = cs;
    __syncthreads();
    for (int s = N_CODES / 2; s > 0; s >>= 1) {
        if (k < s) sh[k] += sh[k + s];
        __syncthreads();
    }
    float n = sh[0];
    __syncthreads();
    float smooth = (cs + EPS_F) / (n + (float)N_CODES * EPS_F) * n;
    g_cs[k] = smooth;
    float p = cnt * (1.0f / (float)N_TOKENS);
    sh[k] = p * logf(p + 1e-10f);
    __syncthreads();
    for (int s = N_CODES / 2; s > 0; s >>= 1) {
        if (k < s) sh[k] += sh[k + s];
        __syncthreads();
    }
    if (k == 0) out_perp[0] = expf(-sh[0]);
}

// ---------------- kernel 5: embedding_new = ema_w_new / cs ----------------
__global__ void embed_new_kernel(const float* __restrict__ ema_w) {
    int i = blockIdx.x * blockDim.x + threadIdx.x;
    if (i >= N_CODES * EMB_DIM) return;
    int k = i >> 6;
    g_embed_new[i] = (ema_w[i] * DECAY_F + OMD_F * g_dw[i]) / g_cs[k];
}

// ---------------- kernel 6: gather quantized + loss partial ----------------
// NOTE: q_out region starts at a 4-byte-aligned offset (out + 1), so ALL
// stores to it must be scalar 32-bit stores. Loads from x/g_embed_new stay
// vectorized (those buffers are 16B-aligned).
__global__ __launch_bounds__(TPB)
void quantize_kernel(const float* __restrict__ x_g,
                     float* __restrict__ q_out) {
    __shared__ float sred[TPB];
    int t = blockIdx.x * TPB + threadIdx.x;
    int idx = g_idx[t];
    const float4* xr = (const float4*)(x_g + (size_t)t * EMB_DIM);
    const float4* qr = (const float4*)(g_embed_new + (size_t)idx * EMB_DIM);
    float* outq = q_out + (size_t)t * EMB_DIM;
    float ss = 0.0f;
#pragma unroll
    for (int j = 0; j < 16; j++) {
        float4 xv = xr[j];
        float4 qv = qr[j];
        outq[4 * j + 0] = qv.x;
        outq[4 * j + 1] = qv.y;
        outq[4 * j + 2] = qv.z;
        outq[4 * j + 3] = qv.w;
        float dx = qv.x - xv.x, dy = qv.y - xv.y;
        float dz = qv.z - xv.z, dw = qv.w - xv.w;
        ss = fmaf(dx, dx, ss); ss = fmaf(dy, dy, ss);
        ss = fmaf(dz, dz, ss); ss = fmaf(dw, dw, ss);
    }
    sred[threadIdx.x] = ss;
    __syncthreads();
    for (int s = TPB / 2; s > 0; s >>= 1) {
        if (threadIdx.x < s) sred[threadIdx.x] += sred[threadIdx.x + s];
        __syncthreads();
    }
    if (threadIdx.x == 0) atomicAdd(&g_loss_accum, sred[0]);
}

// ---------------- kernel 7: finalize loss ----------------
__global__ void finalize_kernel(float* __restrict__ out_loss) {
    out_loss[0] = COMMIT_HALF * g_loss_accum / (float)N_TOKENS;
}

// ---------------- launch ----------------
extern "C" void kernel_launch(void* const* d_in, const int* in_sizes, int n_in,
                              void* d_out, int out_size) {
    const float* inputs  = (const float*)d_in[0];   // [N, 64]
    const float* embed_w = (const float*)d_in[1];   // [1024, 64]
    const float* ema_w   = (const float*)d_in[2];   // [1024, 64]
    const float* ema_cs  = (const float*)d_in[3];   // [1024]

    float* out = (float*)d_out;
    // tuple layout: loss(1) | quantized(N*64) | perplexity(1) | encodings(N*1024)
    float* out_loss = out;
    float* out_q    = out + 1;
    float* out_perp = out + 1 + (size_t)N_TOKENS * EMB_DIM;
    float* out_enc  = out + 2 + (size_t)N_TOKENS * EMB_DIM;

    // zero one-hot encodings region (memset node is graph-capturable)
    cudaMemsetAsync(out_enc, 0, (size_t)N_TOKENS * N_CODES * sizeof(float), 0);

    zero_scratch_kernel<<<(N_CODES * EMB_DIM + 255) / 256, 256>>>();
    prep_h_kernel<<<(N_CODES + 255) / 256, 256>>>(embed_w);
    argmin_kernel<<<N_TOKENS / TPB, TPB>>>(inputs, embed_w, out_enc);
    stats_kernel<<<1, N_CODES>>>(ema_cs, out_perp);
    embed_new_kernel<<<(N_CODES * EMB_DIM + 255) / 256, 256>>>(ema_w);
    quantize_kernel<<<N_TOKENS / TPB, TPB>>>(inputs, out_q);
    finalize_kernel<<<1, 1>>>(out_loss);
}

// round 4
// speedup vs baseline: 1.1529x; 1.1529x over previous
#include <cuda_runtime.h>
#include <cuda_bf16.h>
#include <math.h>
#include <stdint.h>

#define N_TOKENS 131072
#define EMB_DIM  64
#define N_CODES  1024
#define DECAY_F       0.99f
#define OMD_F         ((float)(1.0 - 0.99))
#define EPS_F         1e-5f
#define COMMIT_HALF   0.125f
#define TPB           128

// ===================== device scratch =====================
__device__ int   g_idx[N_TOKENS];
__device__ float g_counts[N_CODES];
__device__ float g_dw[N_CODES * EMB_DIM];
__device__ float g_h[N_CODES];             // 0.5 * ||e_k||^2 (fp32)
__device__ float g_cs[N_CODES];
__device__ float g_embed_new[N_CODES * EMB_DIM];
__device__ float g_loss_accum;
// fragment-ordered bf16 codebook: [chunk(16)][slot(64)=(tile*4+ks)*2+plane][lane(32)] uint2
__device__ uint2 g_Bfrag[16 * 64 * 32];    // 256KB

// ===================== helpers =====================
__device__ __forceinline__ void split2(float x0, float x1, uint32_t& hi, uint32_t& lo) {
    __nv_bfloat16 h0 = __float2bfloat16(x0), h1 = __float2bfloat16(x1);
    __nv_bfloat16 l0 = __float2bfloat16(x0 - __bfloat162float(h0));
    __nv_bfloat16 l1 = __float2bfloat16(x1 - __bfloat162float(h1));
    hi = (uint32_t)__bfloat16_as_ushort(h0) | ((uint32_t)__bfloat16_as_ushort(h1) << 16);
    lo = (uint32_t)__bfloat16_as_ushort(l0) | ((uint32_t)__bfloat16_as_ushort(l1) << 16);
}

__device__ __forceinline__ void mma16816(float* c, const uint32_t* a, uint32_t b0, uint32_t b1) {
    asm volatile(
        "mma.sync.aligned.m16n8k16.row.col.f32.bf16.bf16.f32 "
        "{%0,%1,%2,%3},{%4,%5,%6,%7},{%8,%9},{%0,%1,%2,%3};"
        : "+f"(c[0]), "+f"(c[1]), "+f"(c[2]), "+f"(c[3])
        : "r"(a[0]), "r"(a[1]), "r"(a[2]), "r"(a[3]), "r"(b0), "r"(b1));
}

__device__ __forceinline__ void top2_ins(float v, int i, float& b1, int& i1, float& b2, int& i2) {
    if (v > b1 || (v == b1 && i < i1)) { b2 = b1; i2 = i1; b1 = v; i1 = i; }
    else if (v > b2 || (v == b2 && i < i2)) { b2 = v; i2 = i; }
}

// fp64 re-resolution: val = x.e - 0.5||e||^2 (x fp32 exact from smem)
__device__ double ddot_val(const float* __restrict__ x, const float* __restrict__ e) {
    double dot = 0.0, h = 0.0;
#pragma unroll
    for (int j = 0; j < EMB_DIM; j++) {
        double ev = (double)e[j];
        dot += (double)x[j] * ev;
        h   += ev * ev;
    }
    return dot - 0.5 * h;
}

// ===================== kernel 1: zero scratch =====================
__global__ void zero_scratch_kernel() {
    int i = blockIdx.x * blockDim.x + threadIdx.x;
    if (i < N_CODES) g_counts[i] = 0.0f;
    if (i < N_CODES * EMB_DIM) g_dw[i] = 0.0f;
    if (i == 0) g_loss_accum = 0.0f;
}

// ===================== kernel 2: prep (B fragments + h) =====================
// thread = (n8-tile tn 0..127, lane 0..31)
__global__ void prep_kernel(const float* __restrict__ e) {
    int gid = blockIdx.x * blockDim.x + threadIdx.x;
    if (gid >= 128 * 32) return;
    int tn = gid >> 5, lane = gid & 31;
    int n = tn * 8 + (lane >> 2);
    int chunk = tn >> 3, tilein = tn & 7;
    const float* row = e + (size_t)n * EMB_DIM;
#pragma unroll
    for (int ks = 0; ks < 4; ks++) {
        int k = ks * 16 + (lane & 3) * 2;
        uint32_t h0, l0, h1, l1;
        split2(row[k], row[k + 1], h0, l0);
        split2(row[k + 8], row[k + 9], h1, l1);
        size_t base = ((size_t)chunk * 64 + (size_t)(tilein * 4 + ks) * 2) * 32 + lane;
        g_Bfrag[base]      = make_uint2(h0, h1);   // hi plane (even slot)
        g_Bfrag[base + 32] = make_uint2(l0, l1);   // lo plane (odd slot)
    }
    if ((lane & 3) == 0) {   // one lane per code row computes h
        float s = 0.0f;
#pragma unroll
        for (int j = 0; j < EMB_DIM; j++) s = fmaf(row[j], row[j], s);
        g_h[n] = 0.5f * s;
    }
}

// ===================== kernel 3: argmin via mma.sync + fused one-hot =====================
// smem: x_s[128*64]f (32KB) | h_s[1024]f (4KB) | b_s[2048]uint2 (16KB) | idx_s[128]i (512B)
#define SMEM_SZ (32768 + 4096 + 16384 + 512)

__global__ __launch_bounds__(TPB)
void argmin_mma_kernel(const float* __restrict__ x_g,
                       const float* __restrict__ e_g,
                       float* __restrict__ enc_out) {
    extern __shared__ char smem[];
    float* x_s  = (float*)smem;                     // [128][64]
    float* h_s  = (float*)(smem + 32768);           // [1024]
    uint2* b_s  = (uint2*)(smem + 36864);           // [64][32]
    int*   idx_s = (int*)(smem + 53248);            // [128]

    int tid = threadIdx.x;
    int w = tid >> 5, lane = tid & 31;
    int g = lane >> 2, tg = lane & 3;
    int tb = blockIdx.x * TPB;                      // token block base

    // ---- stage 128 tokens (32KB) + h (4KB) ----
    {
        const uint4* src = (const uint4*)(x_g + (size_t)tb * EMB_DIM);
        uint4* dst = (uint4*)x_s;
#pragma unroll
        for (int i = 0; i < 16; i++) dst[tid + i * TPB] = src[tid + i * TPB];
        for (int i = tid; i < N_CODES; i += TPB) h_s[i] = g_h[i];
    }
    __syncthreads();

    // ---- build A fragments (bf16 hi/lo) in registers ----
    uint32_t ahi[2][4][4], alo[2][4][4];
#pragma unroll
    for (int mt = 0; mt < 2; mt++) {
        int r0 = w * 32 + mt * 16 + g;
        int r1 = r0 + 8;
#pragma unroll
        for (int ks = 0; ks < 4; ks++) {
            int k = ks * 16 + tg * 2;
            split2(x_s[r0 * 64 + k],     x_s[r0 * 64 + k + 1], ahi[mt][ks][0], alo[mt][ks][0]);
            split2(x_s[r1 * 64 + k],     x_s[r1 * 64 + k + 1], ahi[mt][ks][1], alo[mt][ks][1]);
            split2(x_s[r0 * 64 + k + 8], x_s[r0 * 64 + k + 9], ahi[mt][ks][2], alo[mt][ks][2]);
            split2(x_s[r1 * 64 + k + 8], x_s[r1 * 64 + k + 9], ahi[mt][ks][3], alo[mt][ks][3]);
        }
    }

    // trackers: tr = mt*2 + rh; token = w*32 + mt*16 + rh*8 + g
    float b1v[4], b2v[4]; int i1v[4], i2v[4];
#pragma unroll
    for (int t = 0; t < 4; t++) { b1v[t] = -3.4e38f; b2v[t] = -3.4e38f; i1v[t] = 0; i2v[t] = 0; }

    for (int c = 0; c < 16; c++) {
        __syncthreads();
        // cooperative stage of 16KB B chunk
        {
            const uint2* src = &g_Bfrag[(size_t)c * 64 * 32];
#pragma unroll
            for (int i = 0; i < 16; i++) b_s[tid + i * TPB] = src[tid + i * TPB];
        }
        __syncthreads();

        float cc[2][8][4];
#pragma unroll
        for (int mt = 0; mt < 2; mt++)
#pragma unroll
            for (int t = 0; t < 8; t++)
#pragma unroll
                for (int q = 0; q < 4; q++) cc[mt][t][q] = 0.0f;

#pragma unroll
        for (int tile = 0; tile < 8; tile++) {
#pragma unroll
            for (int ks = 0; ks < 4; ks++) {
                uint2 bh = b_s[((tile * 4 + ks) * 2 + 0) * 32 + lane];
                uint2 bl = b_s[((tile * 4 + ks) * 2 + 1) * 32 + lane];
#pragma unroll
                for (int mt = 0; mt < 2; mt++) {
                    mma16816(cc[mt][tile], ahi[mt][ks], bh.x, bh.y);
                    mma16816(cc[mt][tile], ahi[mt][ks], bl.x, bl.y);
                    mma16816(cc[mt][tile], alo[mt][ks], bh.x, bh.y);
                }
            }
        }

        // epilogue: val = dot - h ; update top-2
#pragma unroll
        for (int mt = 0; mt < 2; mt++)
#pragma unroll
            for (int tile = 0; tile < 8; tile++)
#pragma unroll
                for (int rh = 0; rh < 2; rh++)
#pragma unroll
                    for (int j = 0; j < 2; j++) {
                        int n = c * 64 + tile * 8 + tg * 2 + j;
                        float val = cc[mt][tile][rh * 2 + j] - h_s[n];
                        int tr = mt * 2 + rh;
                        top2_ins(val, n, b1v[tr], i1v[tr], b2v[tr], i2v[tr]);
                    }
    }

    // ---- merge top-2 across the quad (lanes sharing g) ----
#pragma unroll
    for (int tr = 0; tr < 4; tr++) {
#pragma unroll
        for (int off = 1; off <= 2; off <<= 1) {
            float ov1 = __shfl_xor_sync(0xFFFFFFFFu, b1v[tr], off);
            int   oi1 = __shfl_xor_sync(0xFFFFFFFFu, i1v[tr], off);
            float ov2 = __shfl_xor_sync(0xFFFFFFFFu, b2v[tr], off);
            int   oi2 = __shfl_xor_sync(0xFFFFFFFFu, i2v[tr], off);
            top2_ins(ov1, oi1, b1v[tr], i1v[tr], b2v[tr], i2v[tr]);
            top2_ins(ov2, oi2, b1v[tr], i1v[tr], b2v[tr], i2v[tr]);
        }
    }

    // ---- owner lanes (tg==0): recheck + scatter ----
    if (tg == 0) {
#pragma unroll
        for (int tr = 0; tr < 4; tr++) {
            int lrow = w * 32 + (tr >> 1) * 16 + (tr & 1) * 8 + g;
            int token = tb + lrow;
            int idx = i1v[tr];
            if (b1v[tr] - b2v[tr] < 1e-2f) {
                const float* xr = &x_s[lrow * 64];
                double v1 = ddot_val(xr, e_g + (size_t)idx * EMB_DIM);
                double v2 = ddot_val(xr, e_g + (size_t)i2v[tr] * EMB_DIM);
                if (v2 > v1 || (v2 == v1 && i2v[tr] < idx)) idx = i2v[tr];
            }
            idx_s[lrow] = idx;
            g_idx[token] = idx;
            atomicAdd(&g_counts[idx], 1.0f);
            float* dwrow = &g_dw[(size_t)idx * EMB_DIM];
            const float* xr = &x_s[lrow * 64];
#pragma unroll
            for (int j = 0; j < EMB_DIM; j++) atomicAdd(&dwrow[j], xr[j]);
        }
    }
    __syncthreads();

    // ---- fused one-hot write (replaces memset): 128 rows x 4KB, coalesced ----
    // enc_out base is only 8B-aligned -> uint2 stores
    {
        int colbase = tid * 8;
        for (int r = 0; r < TPB; r++) {
            int id = idx_s[r];
            float tmp[8];
#pragma unroll
            for (int q = 0; q < 8; q++) tmp[q] = 0.0f;
            int rel = id - colbase;
            if (rel >= 0 && rel < 8) tmp[rel] = 1.0f;
            uint2* dst = (uint2*)(enc_out + (size_t)(tb + r) * N_CODES + colbase);
#pragma unroll
            for (int q = 0; q < 4; q++)
                dst[q] = make_uint2(__float_as_uint(tmp[2 * q]), __float_as_uint(tmp[2 * q + 1]));
        }
    }
}

// ===================== kernel 4: EMA stats + perplexity =====================
__global__ void stats_kernel(const float* __restrict__ ema_cs,
                             float* __restrict__ out_perp) {
    __shared__ float sh[N_CODES];
    int k = threadIdx.x;
    float cnt = g_counts[k];
    float cs = ema_cs[k] * DECAY_F + OMD_F * cnt;
    sh[k] = cs;
    __syncthreads();
    for (int s = N_CODES / 2; s > 0; s >>= 1) {
        if (k < s) sh[k] += sh[k + s];
        __syncthreads();
    }
    float n = sh[0];
    __syncthreads();
    float smooth = (cs + EPS_F) / (n + (float)N_CODES * EPS_F) * n;
    g_cs[k] = smooth;
    float p = cnt * (1.0f / (float)N_TOKENS);
    sh[k] = p * logf(p + 1e-10f);
    __syncthreads();
    for (int s = N_CODES / 2; s > 0; s >>= 1) {
        if (k < s) sh[k] += sh[k + s];
        __syncthreads();
    }
    if (k == 0) out_perp[0] = expf(-sh[0]);
}

// ===================== kernel 5: embedding_new =====================
__global__ void embed_new_kernel(const float* __restrict__ ema_w) {
    int i = blockIdx.x * blockDim.x + threadIdx.x;
    if (i >= N_CODES * EMB_DIM) return;
    int k = i >> 6;
    g_embed_new[i] = (ema_w[i] * DECAY_F + OMD_F * g_dw[i]) / g_cs[k];
}

// ===================== kernel 6: gather quantized + loss =====================
__global__ __launch_bounds__(TPB)
void quantize_kernel(const float* __restrict__ x_g,
                     float* __restrict__ q_out) {
    __shared__ float sred[TPB];
    int t = blockIdx.x * TPB + threadIdx.x;
    int idx = g_idx[t];
    const float4* xr = (const float4*)(x_g + (size_t)t * EMB_DIM);
    const float4* qr = (const float4*)(g_embed_new + (size_t)idx * EMB_DIM);
    float* outq = q_out + (size_t)t * EMB_DIM;   // 4B-aligned region: scalar stores
    float ss = 0.0f;
#pragma unroll
    for (int j = 0; j < 16; j++) {
        float4 xv = xr[j];
        float4 qv = qr[j];
        outq[4 * j + 0] = qv.x; outq[4 * j + 1] = qv.y;
        outq[4 * j + 2] = qv.z; outq[4 * j + 3] = qv.w;
        float dx = qv.x - xv.x, dy = qv.y - xv.y;
        float dz = qv.z - xv.z, dw = qv.w - xv.w;
        ss = fmaf(dx, dx, ss); ss = fmaf(dy, dy, ss);
        ss = fmaf(dz, dz, ss); ss = fmaf(dw, dw, ss);
    }
    sred[threadIdx.x] = ss;
    __syncthreads();
    for (int s = TPB / 2; s > 0; s >>= 1) {
        if (threadIdx.x < s) sred[threadIdx.x] += sred[threadIdx.x + s];
        __syncthreads();
    }
    if (threadIdx.x == 0) atomicAdd(&g_loss_accum, sred[0]);
}

// ===================== kernel 7: finalize loss =====================
__global__ void finalize_kernel(float* __restrict__ out_loss) {
    out_loss[0] = COMMIT_HALF * g_loss_accum / (float)N_TOKENS;
}

// ===================== launch =====================
extern "C" void kernel_launch(void* const* d_in, const int* in_sizes, int n_in,
                              void* d_out, int out_size) {
    const float* inputs  = (const float*)d_in[0];
    const float* embed_w = (const float*)d_in[1];
    const float* ema_w   = (const float*)d_in[2];
    const float* ema_cs  = (const float*)d_in[3];

    float* out = (float*)d_out;
    float* out_loss = out;
    float* out_q    = out + 1;
    float* out_perp = out + 1 + (size_t)N_TOKENS * EMB_DIM;
    float* out_enc  = out + 2 + (size_t)N_TOKENS * EMB_DIM;

    cudaFuncSetAttribute(argmin_mma_kernel,
                         cudaFuncAttributeMaxDynamicSharedMemorySize, SMEM_SZ);

    zero_scratch_kernel<<<(N_CODES * EMB_DIM + 255) / 256, 256>>>();
    prep_kernel<<<16, 256>>>(embed_w);
    argmin_mma_kernel<<<N_TOKENS / TPB, TPB, SMEM_SZ>>>(inputs, embed_w, out_enc);
    stats_kernel<<<1, N_CODES>>>(ema_cs, out_perp);
    embed_new_kernel<<<(N_CODES * EMB_DIM + 255) / 256, 256>>>(ema_w);
    quantize_kernel<<<N_TOKENS / TPB, TPB>>>(inputs, out_q);
    finalize_kernel<<<1, 1>>>(out_loss);
}